// round 13
// baseline (speedup 1.0000x reference)
#include <cuda_runtime.h>

// Problem constants: B=256, T=2048, I=2, H=128, 3H=384
#define BB 256
#define TT 2048
#define HH 128
#define NTHREADS 512

__device__ int d_order[BB];

// Plain descending-length order (R2-proven best): wave 1 = 148 longest,
// wave-2 CTAs work-stolen in bid order = LPT.
__global__ void order_kernel(const int* __restrict__ lengths) {
    int i = threadIdx.x;
    int li = lengths[i];
    int rank = 0;
    #pragma unroll 8
    for (int j = 0; j < BB; j++) {
        int lj = lengths[j];
        rank += (lj > li) || (lj == li && j < i);
    }
    d_order[rank] = i;
}

// ---- packed f32x2 helpers ----
__device__ __forceinline__ unsigned long long fma2(unsigned long long a,
                                                   unsigned long long b,
                                                   unsigned long long c) {
    unsigned long long d;
    asm("fma.rn.f32x2 %0, %1, %2, %3;" : "=l"(d) : "l"(a), "l"(b), "l"(c));
    return d;
}
__device__ __forceinline__ unsigned long long pack2(float x, float y) {
    unsigned long long r;
    asm("mov.b64 %0, {%1, %2};" : "=l"(r) : "f"(x), "f"(y));
    return r;
}
__device__ __forceinline__ void unpack2(unsigned long long v, float& x, float& y) {
    asm("mov.b64 {%0, %1}, %2;" : "=f"(x), "=f"(y) : "l"(v));
}
__device__ __forceinline__ float tanh_fast(float v) {
    float r;
    asm("tanh.approx.f32 %0, %1;" : "=f"(r) : "f"(v));
    return r;
}

// QUARTER split: 512 threads, 16 warps, 4 threads per hidden index j.
//   tid = 128*q + j. Thread owns h-columns [32q, 32q+32) of ALL THREE rows
//   (r_j, z_j, n_j): 48 ull weights = 96 regs -> ~125 regs/thread, within
//   the 128-reg cap at 512 threads (R12 sat at the 255 cap -> spills, MLP=1
//   restarts). LDS/SM/step stays 128; FMA2 floor stays 384 (192/SMSP x rt2).
//   4 warps/SMSP hide the restart LDS latency by interleave.
//   Exchange: q=1..3 publish {pr,pz,pn} via STS.128; named barrier 1+(j>>5)
//   over 128 threads (warps {w',4+w',8+w',12+w'} = all on SMSP w'); q0
//   combines + gates + STS h; one full __syncthreads publishes h.
__global__ void __launch_bounds__(NTHREADS, 1)
gru_kernel(const float* __restrict__ x,        // [B, T, 2]
           const int*   __restrict__ lengths,  // [B]
           const float* __restrict__ W_ih,     // [384, 2]
           const float* __restrict__ W_hh,     // [384, 128]
           const float* __restrict__ b_ih,     // [384]
           const float* __restrict__ b_hh,     // [384]
           const float* __restrict__ head_w,   // [128]
           const float* __restrict__ head_b,   // [1]
           float*       __restrict__ out)      // [B, 1]
{
    __shared__ __align__(16) float sh_x[TT * 2 + 4];  // input seq + pad
    __shared__ __align__(16) float sh_h[2][HH];       // ping-pong hidden state
    __shared__ __align__(16) float4 sh_p[3][HH];      // partials from q=1..3
    __shared__ float sh_red[4];

    const int tid = threadIdx.x;
    const int b = d_order[blockIdx.x];
    const int len = lengths[b];

    const int q = tid >> 7;               // quarter 0..3 (q0 = combiner)
    const int j = tid & 127;
    const int bar_id = 1 + (j >> 5);      // warps {w',4+w',8+w',12+w'}: SMSP w'

    // --- load input prefix into shared ---
    {
        const float4* xs = reinterpret_cast<const float4*>(x + (size_t)b * (TT * 2));
        float4* xd = reinterpret_cast<float4*>(sh_x);
        int nq = (len * 2 + 3) >> 2;
        for (int p = tid; p < nq; p += NTHREADS) xd[p] = xs[p];
        if (tid < 4) sh_x[TT * 2 + tid] = 0.0f;
    }

    // --- weights: own 32-column quarter of rows j, 128+j, 256+j ---
    unsigned long long wr[16], wz[16], wn[16];
    {
        const size_t coff = 32 * q;
        const unsigned long long* pr = reinterpret_cast<const unsigned long long*>(
            W_hh + (size_t)j * HH + coff);
        const unsigned long long* pz = reinterpret_cast<const unsigned long long*>(
            W_hh + (size_t)(HH + j) * HH + coff);
        const unsigned long long* pn = reinterpret_cast<const unsigned long long*>(
            W_hh + (size_t)(2 * HH + j) * HH + coff);
        #pragma unroll
        for (int k = 0; k < 16; k++) { wr[k] = pr[k]; wz[k] = pz[k]; wn[k] = pn[k]; }
    }

    // n-row hidden bias: folded into q0's aN accumulator init.
    const unsigned long long bN2 = pack2(q ? 0.0f : b_hh[2 * HH + j], 0.0f);
    const unsigned long long zero2 = pack2(0.0f, 0.0f);

    // Input-projection constants (q0 only; zeros elsewhere -> branch-free
    // x-proj). sigma prescale (0.5) folded into r,z; BOTH biases (b_ih+b_hh)
    // folded into the r/z constants; n keeps b_ih only (b_hh_n in bN2).
    float rw0 = 0.f, rw1 = 0.f, rb = 0.f;
    float zw0 = 0.f, zw1 = 0.f, zb = 0.f;
    float nw0 = 0.f, nw1 = 0.f, nb = 0.f;
    float h = 0.0f;
    if (q == 0) {
        float2 t2 = *reinterpret_cast<const float2*>(W_ih + (size_t)j * 2);
        rw0 = 0.5f * t2.x; rw1 = 0.5f * t2.y;
        rb = 0.5f * (b_ih[j] + b_hh[j]);
        t2 = *reinterpret_cast<const float2*>(W_ih + (size_t)(HH + j) * 2);
        zw0 = 0.5f * t2.x; zw1 = 0.5f * t2.y;
        zb = 0.5f * (b_ih[HH + j] + b_hh[HH + j]);
        t2 = *reinterpret_cast<const float2*>(W_ih + (size_t)(2 * HH + j) * 2);
        nw0 = t2.x; nw1 = t2.y;
        nb = b_ih[2 * HH + j];
        sh_h[0][j] = 0.0f;
    }
    __syncthreads();

    int cur = 0;
    for (int t = 0; t < len; t++) {
        // x projections (broadcast LDS.64; h-independent).
        float2 xt = *reinterpret_cast<const float2*>(sh_x + 2 * t);
        float xr2 = fmaf(rw0, xt.x, fmaf(rw1, xt.y, rb));
        float xz2 = fmaf(zw0, xt.x, fmaf(zw1, xt.y, zb));
        float xn  = fmaf(nw0, xt.x, fmaf(nw1, xt.y, nb));

        // Matvec over own 32-col quarter: h chunk loaded once, reused x3.
        // 3 chains; same-chain distance 3 ops x rt2 = 6 cyc >= lat.
        unsigned long long aR = zero2, aZ = zero2, aN = bN2;
        const ulonglong2* hseg =
            reinterpret_cast<const ulonglong2*>(sh_h[cur] + 32 * q);
        #pragma unroll
        for (int k = 0; k < 8; k++) {
            ulonglong2 hv = hseg[k];            // LDS.128 (4 h values)
            aR = fma2(wr[2 * k],     hv.x, aR);
            aZ = fma2(wz[2 * k],     hv.x, aZ);
            aN = fma2(wn[2 * k],     hv.x, aN);
            aR = fma2(wr[2 * k + 1], hv.y, aR);
            aZ = fma2(wz[2 * k + 1], hv.y, aZ);
            aN = fma2(wn[2 * k + 1], hv.y, aN);
        }
        float ra, rbv, za, zbv, na, nbv;
        unpack2(aR, ra, rbv);
        unpack2(aZ, za, zbv);
        unpack2(aN, na, nbv);
        float pr = ra + rbv, pz = za + zbv, pn = na + nbv;

        if (q) {
            sh_p[q - 1][j] = make_float4(pr, pz, pn, 0.0f);
            asm volatile("bar.arrive %0, 128;" :: "r"(bar_id) : "memory");
            __syncthreads();
        } else {
            asm volatile("bar.sync %0, 128;" :: "r"(bar_id) : "memory");
            float4 p0 = sh_p[0][j];
            float4 p1 = sh_p[1][j];
            float4 p2 = sh_p[2][j];
            float gr = (pr + p0.x) + (p1.x + p2.x);
            float gz = (pz + p0.y) + (p1.y + p2.y);
            float gn = (pn + p0.z) + (p1.z + p2.z);
            float r_t = tanh_fast(fmaf(0.5f, gr, xr2));
            float z_t = tanh_fast(fmaf(0.5f, gz, xz2));
            float gnh = 0.5f * gn;
            float n = tanh_fast(fmaf(r_t, gnh, xn + gnh));  // tanh(xn + r*gn)
            h = 0.5f * fmaf(z_t, h - n, h + n);             // (1-z)*n + z*h
            sh_h[cur ^ 1][j] = h;
            __syncthreads();
        }
        cur ^= 1;
    }

    // --- head: out[b] = sum_j h[j]*head_w[j] + head_b (q0 holds h) ---
    if (tid < HH) {
        float v = h * head_w[j];
        #pragma unroll
        for (int o = 16; o > 0; o >>= 1) v += __shfl_down_sync(0xffffffffu, v, o);
        if ((tid & 31) == 0) sh_red[tid >> 5] = v;
    }
    __syncthreads();
    if (tid == 0) {
        out[b] = (sh_red[0] + sh_red[1]) + (sh_red[2] + sh_red[3]) + head_b[0];
    }
}

extern "C" void kernel_launch(void* const* d_in, const int* in_sizes, int n_in,
                              void* d_out, int out_size) {
    const float* x      = (const float*)d_in[0];
    const int*   len    = (const int*)  d_in[1];
    const float* W_ih   = (const float*)d_in[2];
    const float* W_hh   = (const float*)d_in[3];
    const float* b_ih   = (const float*)d_in[4];
    const float* b_hh   = (const float*)d_in[5];
    const float* head_w = (const float*)d_in[6];
    const float* head_b = (const float*)d_in[7];
    float* out = (float*)d_out;

    order_kernel<<<1, BB>>>(len);
    gru_kernel<<<BB, NTHREADS>>>(x, len, W_ih, W_hh, b_ih, b_hh,
                                 head_w, head_b, out);
}

// round 14
// speedup vs baseline: 1.2012x; 1.2012x over previous
#include <cuda_runtime.h>

// Problem constants: B=256, T=2048, I=2, H=128, 3H=384
#define BB 256
#define TT 2048
#define HH 128
#define NTHREADS 256

__device__ int d_order[BB];

// Plain descending-length order (R2-proven best): wave 1 = 148 longest,
// wave-2 CTAs work-stolen in bid order = LPT.
__global__ void order_kernel(const int* __restrict__ lengths) {
    int i = threadIdx.x;
    int li = lengths[i];
    int rank = 0;
    #pragma unroll 8
    for (int j = 0; j < BB; j++) {
        int lj = lengths[j];
        rank += (lj > li) || (lj == li && j < i);
    }
    d_order[rank] = i;
}

// ---- packed f32x2 helpers ----
__device__ __forceinline__ unsigned long long fma2(unsigned long long a,
                                                   unsigned long long b,
                                                   unsigned long long c) {
    unsigned long long d;
    asm("fma.rn.f32x2 %0, %1, %2, %3;" : "=l"(d) : "l"(a), "l"(b), "l"(c));
    return d;
}
__device__ __forceinline__ unsigned long long add2(unsigned long long a,
                                                   unsigned long long b) {
    unsigned long long d;
    asm("add.rn.f32x2 %0, %1, %2;" : "=l"(d) : "l"(a), "l"(b));
    return d;
}
__device__ __forceinline__ unsigned long long pack2(float x, float y) {
    unsigned long long r;
    asm("mov.b64 %0, {%1, %2};" : "=l"(r) : "f"(x), "f"(y));
    return r;
}
__device__ __forceinline__ void unpack2(unsigned long long v, float& x, float& y) {
    asm("mov.b64 {%0, %1}, %2;" : "=f"(x), "=f"(y) : "l"(v));
}
__device__ __forceinline__ float tanh_fast(float v) {
    float r;
    asm("tanh.approx.f32 %0, %1;" : "=f"(r) : "f"(v));
    return r;
}

// TRI-ROW HALF-COLUMN (R12 champion) + dependency-exact barriers.
//   tid = 128*half + j. Thread owns h-cols [64h, 64h+64) of rows r_j,z_j,n_j:
//   h chunk loaded once (16 LDS.128), reused x3 -> LDS/SM/step = 128, under
//   the 384-cyc FMA2 floor (2 warps/SMSP x 96 x rt2).
// Barriers per step:
//   pair bar 1+w (64 thr, warps w & w+4): partials upper -> lower.
//   bar5 (128 thr, warps 0-3 sync): h[0:64) publish to lower consumers.
//   bar6 (192 thr, warps 2,3 arrive + warps 4-7 sync): h[64:128) to upper.
// Upper no longer waits on warps 0,1's gate tails; lower never waits on upper.
__global__ void __launch_bounds__(NTHREADS, 1)
gru_kernel(const float* __restrict__ x,        // [B, T, 2]
           const int*   __restrict__ lengths,  // [B]
           const float* __restrict__ W_ih,     // [384, 2]
           const float* __restrict__ W_hh,     // [384, 128]
           const float* __restrict__ b_ih,     // [384]
           const float* __restrict__ b_hh,     // [384]
           const float* __restrict__ head_w,   // [128]
           const float* __restrict__ head_b,   // [1]
           float*       __restrict__ out)      // [B, 1]
{
    __shared__ __align__(16) float sh_x[TT * 2 + 4];  // input seq + pad
    __shared__ __align__(16) float sh_h[2][HH];       // ping-pong hidden state
    __shared__ __align__(16) float4 sh_p[HH];         // upper-half partials
    __shared__ float sh_red[4];

    const int tid = threadIdx.x;
    const int b = d_order[blockIdx.x];
    const int len = lengths[b];

    const int half = tid >> 7;            // 0 = lower/combiner, 1 = upper
    const int j = tid & 127;
    const int bar_id = 1 + ((tid >> 5) & 3);

    // --- load input prefix into shared ---
    {
        const float4* xs = reinterpret_cast<const float4*>(x + (size_t)b * (TT * 2));
        float4* xd = reinterpret_cast<float4*>(sh_x);
        int nq = (len * 2 + 3) >> 2;
        for (int q = tid; q < nq; q += NTHREADS) xd[q] = xs[q];
        if (tid < 4) sh_x[TT * 2 + tid] = 0.0f;
    }

    // --- weights: own 64-column half of rows j, 128+j, 256+j ---
    unsigned long long wr[32], wz[32], wn[32];
    {
        const size_t coff = 64 * half;
        const unsigned long long* pr = reinterpret_cast<const unsigned long long*>(
            W_hh + (size_t)j * HH + coff);
        const unsigned long long* pz = reinterpret_cast<const unsigned long long*>(
            W_hh + (size_t)(HH + j) * HH + coff);
        const unsigned long long* pn = reinterpret_cast<const unsigned long long*>(
            W_hh + (size_t)(2 * HH + j) * HH + coff);
        #pragma unroll
        for (int k = 0; k < 32; k++) { wr[k] = pr[k]; wz[k] = pz[k]; wn[k] = pn[k]; }
    }

    // b_hh_n must stay inside gn (it is multiplied by r); fold into lower's
    // aN init. r/z hidden biases are folded into the sigma constants below.
    const unsigned long long bN2 = pack2(half ? 0.0f : b_hh[2 * HH + j], 0.0f);
    const unsigned long long zero2 = pack2(0.0f, 0.0f);

    // Input-projection constants (lower half only; zeros on upper ->
    // branch-free x-proj). sigma prescale (0.5) folded into r,z; both
    // biases (b_ih + b_hh) folded for r,z.
    float rw0 = 0.f, rw1 = 0.f, rb = 0.f;
    float zw0 = 0.f, zw1 = 0.f, zb = 0.f;
    float nw0 = 0.f, nw1 = 0.f, nb = 0.f;
    float h = 0.0f;
    if (!half) {
        float2 t2 = *reinterpret_cast<const float2*>(W_ih + (size_t)j * 2);
        rw0 = 0.5f * t2.x; rw1 = 0.5f * t2.y;
        rb = 0.5f * (b_ih[j] + b_hh[j]);
        t2 = *reinterpret_cast<const float2*>(W_ih + (size_t)(HH + j) * 2);
        zw0 = 0.5f * t2.x; zw1 = 0.5f * t2.y;
        zb = 0.5f * (b_ih[HH + j] + b_hh[HH + j]);
        t2 = *reinterpret_cast<const float2*>(W_ih + (size_t)(2 * HH + j) * 2);
        nw0 = t2.x; nw1 = t2.y;
        nb = b_ih[2 * HH + j];
        sh_h[0][j] = 0.0f;
    }
    __syncthreads();

    int cur = 0;
    for (int t = 0; t < len; t++) {
        // x projections (broadcast LDS.64; h-independent).
        float2 xt = *reinterpret_cast<const float2*>(sh_x + 2 * t);
        float xr2 = fmaf(rw0, xt.x, fmaf(rw1, xt.y, rb));
        float xz2 = fmaf(zw0, xt.x, fmaf(zw1, xt.y, zb));
        float xn  = fmaf(nw0, xt.x, fmaf(nw1, xt.y, nb));

        // Matvec over own 64-col half: h chunk loaded once, reused x3.
        unsigned long long aR0 = zero2, aR1 = zero2;
        unsigned long long aZ0 = zero2, aZ1 = zero2;
        unsigned long long aN0 = bN2,  aN1 = zero2;
        const ulonglong2* hseg =
            reinterpret_cast<const ulonglong2*>(sh_h[cur] + 64 * half);
        #pragma unroll
        for (int k = 0; k < 16; k++) {
            ulonglong2 hv = hseg[k];            // LDS.128 (4 h values)
            aR0 = fma2(wr[2 * k],     hv.x, aR0);
            aZ0 = fma2(wz[2 * k],     hv.x, aZ0);
            aN0 = fma2(wn[2 * k],     hv.x, aN0);
            aR1 = fma2(wr[2 * k + 1], hv.y, aR1);
            aZ1 = fma2(wz[2 * k + 1], hv.y, aZ1);
            aN1 = fma2(wn[2 * k + 1], hv.y, aN1);
        }
        unsigned long long sR = add2(aR0, aR1);
        unsigned long long sZ = add2(aZ0, aZ1);
        unsigned long long sN = add2(aN0, aN1);
        float ra, rbv, za, zbv, na, nbv;
        unpack2(sR, ra, rbv);
        unpack2(sZ, za, zbv);
        unpack2(sN, na, nbv);
        float pr = ra + rbv, pz = za + zbv, pn = na + nbv;

        if (half) {
            // Publish partials -> pair bar; wait for h[64:128) on bar6.
            sh_p[j] = make_float4(pr, pz, pn, 0.0f);
            asm volatile("bar.arrive %0, 64;" :: "r"(bar_id) : "memory");
            asm volatile("bar.sync 6, 192;" ::: "memory");
        } else {
            asm volatile("bar.sync %0, 64;" :: "r"(bar_id) : "memory");
            float4 p = sh_p[j];
            float gr = pr + p.x;
            float gz = pz + p.y;
            float gn = pn + p.z;
            float r_t = tanh_fast(fmaf(0.5f, gr, xr2));
            float z_t = tanh_fast(fmaf(0.5f, gz, xz2));
            float gnh = 0.5f * gn;
            float n = tanh_fast(fmaf(r_t, gnh, xn + gnh));  // tanh(xn + r*gn)
            h = 0.5f * fmaf(z_t, h - n, h + n);             // (1-z)*n + z*h
            sh_h[cur ^ 1][j] = h;
            // warps 2,3 (j >= 64) feed the upper consumers: predicated
            // arrive on bar6 (no BSSY), then all lower warps sync bar5.
            asm volatile(
                "{\n\t"
                ".reg .pred p;\n\t"
                "setp.ge.s32 p, %0, 64;\n\t"
                "@p bar.arrive 6, 192;\n\t"
                "bar.sync 5, 128;\n\t"
                "}" :: "r"(j) : "memory");
        }
        cur ^= 1;
    }

    // --- head: out[b] = sum_j h[j]*head_w[j] + head_b (lower half holds h) ---
    __syncthreads();
    if (!half) {
        float v = h * head_w[j];
        #pragma unroll
        for (int o = 16; o > 0; o >>= 1) v += __shfl_down_sync(0xffffffffu, v, o);
        if ((tid & 31) == 0) sh_red[tid >> 5] = v;
    }
    __syncthreads();
    if (tid == 0) {
        out[b] = (sh_red[0] + sh_red[1]) + (sh_red[2] + sh_red[3]) + head_b[0];
    }
}

extern "C" void kernel_launch(void* const* d_in, const int* in_sizes, int n_in,
                              void* d_out, int out_size) {
    const float* x      = (const float*)d_in[0];
    const int*   len    = (const int*)  d_in[1];
    const float* W_ih   = (const float*)d_in[2];
    const float* W_hh   = (const float*)d_in[3];
    const float* b_ih   = (const float*)d_in[4];
    const float* b_hh   = (const float*)d_in[5];
    const float* head_w = (const float*)d_in[6];
    const float* head_b = (const float*)d_in[7];
    float* out = (float*)d_out;

    order_kernel<<<1, BB>>>(len);
    gru_kernel<<<BB, NTHREADS>>>(x, len, W_ih, W_hh, b_ih, b_hh,
                                 head_w, head_b, out);
}

// round 15
// speedup vs baseline: 1.2737x; 1.0604x over previous
#include <cuda_runtime.h>

// Problem constants: B=256, T=2048, I=2, H=128, 3H=384
#define BB 256
#define TT 2048
#define HH 128
#define NTHREADS 256
#define LCOLS 56            // lower half's columns  [0, 56)
#define UCOLS 72            // upper half's columns  [56, 128)

__device__ int d_order[BB];

// Plain descending-length order (R2-proven best): wave 1 = 148 longest,
// wave-2 CTAs work-stolen in bid order = LPT.
__global__ void order_kernel(const int* __restrict__ lengths) {
    int i = threadIdx.x;
    int li = lengths[i];
    int rank = 0;
    #pragma unroll 8
    for (int j = 0; j < BB; j++) {
        int lj = lengths[j];
        rank += (lj > li) || (lj == li && j < i);
    }
    d_order[rank] = i;
}

// ---- packed f32x2 helpers ----
__device__ __forceinline__ unsigned long long fma2(unsigned long long a,
                                                   unsigned long long b,
                                                   unsigned long long c) {
    unsigned long long d;
    asm("fma.rn.f32x2 %0, %1, %2, %3;" : "=l"(d) : "l"(a), "l"(b), "l"(c));
    return d;
}
__device__ __forceinline__ unsigned long long add2(unsigned long long a,
                                                   unsigned long long b) {
    unsigned long long d;
    asm("add.rn.f32x2 %0, %1, %2;" : "=l"(d) : "l"(a), "l"(b));
    return d;
}
__device__ __forceinline__ unsigned long long pack2(float x, float y) {
    unsigned long long r;
    asm("mov.b64 %0, {%1, %2};" : "=l"(r) : "f"(x), "f"(y));
    return r;
}
__device__ __forceinline__ void unpack2(unsigned long long v, float& x, float& y) {
    asm("mov.b64 {%0, %1}, %2;" : "=f"(x), "=f"(y) : "l"(v));
}
__device__ __forceinline__ float tanh_fast(float v) {
    float r;
    asm("tanh.approx.f32 %0, %1;" : "=f"(r) : "f"(v));
    return r;
}

// ASYMMETRIC TRI-ROW SPLIT (evolves R12/R14 champion):
//   lower (tid 0..127, warps 0-3): cols [0,56) of rows r_j,z_j,n_j (84 FMA2)
//        + full gate computation for its j. 168 weight regs.
//   upper (tid 128..255, warps 4-7): cols [56,128) (108 FMA2). 216 w-regs.
//   Arbiter is hi-wid-first -> upper's 108 FMA2 drain FIRST (~324 cyc),
//   partials published ~250 cyc before lower finishes (576) -> lower's
//   pair-bar is a fall-through instead of a ~50-cyc wait.
// Barriers/step: pair bar 1+w (64 thr, warps w & w+4) partials upper->lower;
//   bar5 (128, lower-only) h publish for lower restart;
//   bar6 (256, lower arrives post-gate, upper syncs) h for upper restart.
// sh_p and sh_h are ping-ponged; ordering chains verified (no WAR races).
__global__ void __launch_bounds__(NTHREADS, 1)
gru_kernel(const float* __restrict__ x,        // [B, T, 2]
           const int*   __restrict__ lengths,  // [B]
           const float* __restrict__ W_ih,     // [384, 2]
           const float* __restrict__ W_hh,     // [384, 128]
           const float* __restrict__ b_ih,     // [384]
           const float* __restrict__ b_hh,     // [384]
           const float* __restrict__ head_w,   // [128]
           const float* __restrict__ head_b,   // [1]
           float*       __restrict__ out)      // [B, 1]
{
    __shared__ __align__(16) float sh_x[TT * 2 + 4];   // input seq + pad
    __shared__ __align__(16) float sh_h[2][HH];        // ping-pong hidden
    __shared__ __align__(16) float4 sh_p[2][HH];       // ping-pong partials
    __shared__ float sh_red[4];

    const int tid = threadIdx.x;
    const int b = d_order[blockIdx.x];
    const int len = lengths[b];

    const int half = tid >> 7;            // 0 = lower/combiner, 1 = upper
    const int j = tid & 127;
    const int bar_id = 1 + ((tid >> 5) & 3);

    // --- load input prefix into shared ---
    {
        const float4* xs = reinterpret_cast<const float4*>(x + (size_t)b * (TT * 2));
        float4* xd = reinterpret_cast<float4*>(sh_x);
        int nq = (len * 2 + 3) >> 2;
        for (int q = tid; q < nq; q += NTHREADS) xd[q] = xs[q];
        if (tid < 4) sh_x[TT * 2 + tid] = 0.0f;
    }

    if (half) {
        // ================= UPPER: cols [56,128) of the 3 rows ==============
        unsigned long long wr[UCOLS / 2], wz[UCOLS / 2], wn[UCOLS / 2];
        {
            const unsigned long long* pr = reinterpret_cast<const unsigned long long*>(
                W_hh + (size_t)j * HH + LCOLS);
            const unsigned long long* pz = reinterpret_cast<const unsigned long long*>(
                W_hh + (size_t)(HH + j) * HH + LCOLS);
            const unsigned long long* pn = reinterpret_cast<const unsigned long long*>(
                W_hh + (size_t)(2 * HH + j) * HH + LCOLS);
            #pragma unroll
            for (int k = 0; k < UCOLS / 2; k++) {
                wr[k] = pr[k]; wz[k] = pz[k]; wn[k] = pn[k];
            }
        }
        const unsigned long long zero2 = pack2(0.0f, 0.0f);
        __syncthreads();

        int cur = 0;
        for (int t = 0; t < len; t++) {
            unsigned long long aR0 = zero2, aR1 = zero2;
            unsigned long long aZ0 = zero2, aZ1 = zero2;
            unsigned long long aN0 = zero2, aN1 = zero2;
            const ulonglong2* hseg =
                reinterpret_cast<const ulonglong2*>(sh_h[cur] + LCOLS);
            #pragma unroll
            for (int k = 0; k < UCOLS / 4; k++) {      // 18 LDS.128
                ulonglong2 hv = hseg[k];
                aR0 = fma2(wr[2 * k],     hv.x, aR0);
                aZ0 = fma2(wz[2 * k],     hv.x, aZ0);
                aN0 = fma2(wn[2 * k],     hv.x, aN0);
                aR1 = fma2(wr[2 * k + 1], hv.y, aR1);
                aZ1 = fma2(wz[2 * k + 1], hv.y, aZ1);
                aN1 = fma2(wn[2 * k + 1], hv.y, aN1);
            }
            unsigned long long sR = add2(aR0, aR1);
            unsigned long long sZ = add2(aZ0, aZ1);
            unsigned long long sN = add2(aN0, aN1);
            float ra, rbv, za, zbv, na, nbv;
            unpack2(sR, ra, rbv);
            unpack2(sZ, za, zbv);
            unpack2(sN, na, nbv);
            sh_p[cur][j] = make_float4(ra + rbv, za + zbv, na + nbv, 0.0f);
            asm volatile("bar.arrive %0, 64;" :: "r"(bar_id) : "memory");
            asm volatile("bar.sync 6, 256;" ::: "memory");   // wait h[56:128)
            cur ^= 1;
        }
    } else {
        // ================= LOWER: cols [0,56) + gates ======================
        unsigned long long wr[LCOLS / 2], wz[LCOLS / 2], wn[LCOLS / 2];
        {
            const unsigned long long* pr = reinterpret_cast<const unsigned long long*>(
                W_hh + (size_t)j * HH);
            const unsigned long long* pz = reinterpret_cast<const unsigned long long*>(
                W_hh + (size_t)(HH + j) * HH);
            const unsigned long long* pn = reinterpret_cast<const unsigned long long*>(
                W_hh + (size_t)(2 * HH + j) * HH);
            #pragma unroll
            for (int k = 0; k < LCOLS / 2; k++) {
                wr[k] = pr[k]; wz[k] = pz[k]; wn[k] = pn[k];
            }
        }
        const unsigned long long bN2 = pack2(b_hh[2 * HH + j], 0.0f);
        const unsigned long long zero2 = pack2(0.0f, 0.0f);

        // sigma prescale (0.5) folded into r,z; both biases folded for r,z.
        float rw0, rw1, rb, zw0, zw1, zb, nw0, nw1, nb;
        {
            float2 t2 = *reinterpret_cast<const float2*>(W_ih + (size_t)j * 2);
            rw0 = 0.5f * t2.x; rw1 = 0.5f * t2.y;
            rb = 0.5f * (b_ih[j] + b_hh[j]);
            t2 = *reinterpret_cast<const float2*>(W_ih + (size_t)(HH + j) * 2);
            zw0 = 0.5f * t2.x; zw1 = 0.5f * t2.y;
            zb = 0.5f * (b_ih[HH + j] + b_hh[HH + j]);
            t2 = *reinterpret_cast<const float2*>(W_ih + (size_t)(2 * HH + j) * 2);
            nw0 = t2.x; nw1 = t2.y;
            nb = b_ih[2 * HH + j];
        }
        float h = 0.0f;
        sh_h[0][j] = 0.0f;
        __syncthreads();

        int cur = 0;
        for (int t = 0; t < len; t++) {
            float2 xt = *reinterpret_cast<const float2*>(sh_x + 2 * t);
            float xr2 = fmaf(rw0, xt.x, fmaf(rw1, xt.y, rb));
            float xz2 = fmaf(zw0, xt.x, fmaf(zw1, xt.y, zb));
            float xn  = fmaf(nw0, xt.x, fmaf(nw1, xt.y, nb));

            unsigned long long aR0 = zero2, aR1 = zero2;
            unsigned long long aZ0 = zero2, aZ1 = zero2;
            unsigned long long aN0 = bN2,  aN1 = zero2;
            const ulonglong2* hseg =
                reinterpret_cast<const ulonglong2*>(sh_h[cur]);
            #pragma unroll
            for (int k = 0; k < LCOLS / 4; k++) {      // 14 LDS.128
                ulonglong2 hv = hseg[k];
                aR0 = fma2(wr[2 * k],     hv.x, aR0);
                aZ0 = fma2(wz[2 * k],     hv.x, aZ0);
                aN0 = fma2(wn[2 * k],     hv.x, aN0);
                aR1 = fma2(wr[2 * k + 1], hv.y, aR1);
                aZ1 = fma2(wz[2 * k + 1], hv.y, aZ1);
                aN1 = fma2(wn[2 * k + 1], hv.y, aN1);
            }
            unsigned long long sR = add2(aR0, aR1);
            unsigned long long sZ = add2(aZ0, aZ1);
            unsigned long long sN = add2(aN0, aN1);
            float ra, rbv, za, zbv, na, nbv;
            unpack2(sR, ra, rbv);
            unpack2(sZ, za, zbv);
            unpack2(sN, na, nbv);

            // Upper published ~250 cyc ago: fast-path sync.
            asm volatile("bar.sync %0, 64;" :: "r"(bar_id) : "memory");
            float4 p = sh_p[cur][j];
            float gr = (ra + rbv) + p.x;
            float gz = (za + zbv) + p.y;
            float gn = (na + nbv) + p.z;
            float r_t = tanh_fast(fmaf(0.5f, gr, xr2));
            float z_t = tanh_fast(fmaf(0.5f, gz, xz2));
            float gnh = 0.5f * gn;
            float n = tanh_fast(fmaf(r_t, gnh, xn + gnh));  // tanh(xn + r*gn)
            h = 0.5f * fmaf(z_t, h - n, h + n);             // (1-z)*n + z*h
            sh_h[cur ^ 1][j] = h;
            // Publish h: arrive bar6 (upper restart), sync bar5 (lower).
            asm volatile("bar.arrive 6, 256;" ::: "memory");
            asm volatile("bar.sync 5, 128;" ::: "memory");
            cur ^= 1;
        }

        // --- head partial (lower holds h) ---
        float v = h * head_w[j];
        #pragma unroll
        for (int o = 16; o > 0; o >>= 1) v += __shfl_down_sync(0xffffffffu, v, o);
        if ((tid & 31) == 0) sh_red[tid >> 5] = v;
    }

    __syncthreads();
    if (tid == 0) {
        out[b] = (sh_red[0] + sh_red[1]) + (sh_red[2] + sh_red[3]) + head_b[0];
    }
}

extern "C" void kernel_launch(void* const* d_in, const int* in_sizes, int n_in,
                              void* d_out, int out_size) {
    const float* x      = (const float*)d_in[0];
    const int*   len    = (const int*)  d_in[1];
    const float* W_ih   = (const float*)d_in[2];
    const float* W_hh   = (const float*)d_in[3];
    const float* b_ih   = (const float*)d_in[4];
    const float* b_hh   = (const float*)d_in[5];
    const float* head_w = (const float*)d_in[6];
    const float* head_b = (const float*)d_in[7];
    float* out = (float*)d_out;

    order_kernel<<<1, BB>>>(len);
    gru_kernel<<<BB, NTHREADS>>>(x, len, W_ih, W_hh, b_ih, b_hh,
                                 head_w, head_b, out);
}